// round 15
// baseline (speedup 1.0000x reference)
#include <cuda_runtime.h>
#include <cuda_fp16.h>
#include <math.h>
#include <stdint.h>

// ---------------------------------------------------------------------------
// Problem constants
// ---------------------------------------------------------------------------
#define HID    4096
#define SEQ    2048
#define BATCH  2
#define NHEADS 32
#define NKV    8
#define HD     128
#define KVW    (NKV * HD)        // 1024
#define MROWS  (BATCH * SEQ)     // 4096
#define NQKV   (HID + 2 * KVW)   // 6144
#define MAXPOS 4096

// ---------------------------------------------------------------------------
// Scratch (device globals: no allocation allowed) — fp16 operands
// ---------------------------------------------------------------------------
__device__ __half g_X   [(size_t)MROWS * HID];
__device__ __half g_Wqkv[(size_t)NQKV * HID];   // [n][k] transposed weights
__device__ __half g_Wo  [(size_t)HID * HID];
__device__ __half g_Q   [(size_t)MROWS * HID];
__device__ __half g_K   [(size_t)MROWS * KVW];
__device__ __half g_V   [(size_t)MROWS * KVW];
__device__ __half g_Vt  [(size_t)MROWS * KVW];  // [b*8+kvh][d][seq]
__device__ __half g_A   [(size_t)MROWS * HID];
__device__ float  g_sin [MAXPOS * 64];
__device__ float  g_cos [MAXPOS * 64];

// ---------------------------------------------------------------------------
// helpers
// ---------------------------------------------------------------------------
__global__ void f2h_kernel(const float* __restrict__ in,
                           __half* __restrict__ out, int n4)
{
    int i = blockIdx.x * blockDim.x + threadIdx.x;
    if (i >= n4) return;
    float4 v = ((const float4*)in)[i];
    __half2* o = (__half2*)(out + 4 * (size_t)i);
    o[0] = __floats2half2_rn(v.x, v.y);
    o[1] = __floats2half2_rn(v.z, v.w);
}

// fused transpose + convert of all 4 weight matrices (z selects matrix)
__global__ void transpose_all(const float* __restrict__ Wq,
                              const float* __restrict__ Wk,
                              const float* __restrict__ Wv,
                              const float* __restrict__ Wo,
                              __half* __restrict__ Wqkv,
                              __half* __restrict__ Woh)
{
    __shared__ float t[32][33];
    const int z = blockIdx.z;
    const float* in; __half* out; int N;
    if (z == 0)      { in = Wq; out = Wqkv;                              N = HID; }
    else if (z == 1) { in = Wk; out = Wqkv + (size_t)HID * HID;          N = KVW; }
    else if (z == 2) { in = Wv; out = Wqkv + (size_t)(HID + KVW) * HID;  N = KVW; }
    else             { in = Wo; out = Woh;                               N = HID; }
    int n0 = blockIdx.x * 32;
    if (n0 >= N) return;
    int k0 = blockIdx.y * 32;
    int x = threadIdx.x, y = threadIdx.y;   // 32 x 8
#pragma unroll
    for (int i = 0; i < 32; i += 8)
        t[y + i][x] = in[(size_t)(k0 + y + i) * N + n0 + x];
    __syncthreads();
#pragma unroll
    for (int i = 0; i < 32; i += 8)
        out[(size_t)(n0 + y + i) * HID + k0 + x] = __float2half_rn(t[x][y + i]);
}

// V transpose: Vt[b*8+kvh][d][s] = V[(b*SEQ+s)][kvh*128+d]
__global__ void vtrans_kernel(const __half* __restrict__ V,
                              __half* __restrict__ Vt)
{
    __shared__ __half t[32][33];
    int p = blockIdx.z;
    int b = p >> 3, kvh = p & 7;
    int s0 = blockIdx.x * 32, d0 = blockIdx.y * 32;
    int x = threadIdx.x, y = threadIdx.y;
#pragma unroll
    for (int i = 0; i < 32; i += 8)
        t[y + i][x] = V[(size_t)(b * SEQ + s0 + y + i) * KVW + kvh * 128 + d0 + x];
    __syncthreads();
#pragma unroll
    for (int i = 0; i < 32; i += 8)
        Vt[((size_t)p * 128 + d0 + y + i) * SEQ + s0 + x] = t[x][y + i];
}

// RoPE sin/cos table build (bit-identical math to per-element path)
__global__ void rope_table_kernel(float* __restrict__ stab,
                                  float* __restrict__ ctab)
{
    int i = blockIdx.x * blockDim.x + threadIdx.x;
    if (i >= MAXPOS * 64) return;
    int p = i >> 6, d = i & 63;
    double inv = pow(10000.0, -((double)d) / 64.0);
    float ang = (float)((double)p * inv);
    stab[i] = sinf(ang);
    ctab[i] = cosf(ang);
}

// RoPE apply (in-place on fp16, pair-safe), table-driven.
__global__ void rope_h(__half* __restrict__ T, const int* __restrict__ pos_ids,
                       const float* __restrict__ stab,
                       const float* __restrict__ ctab,
                       int cols, int npairs)
{
    int idx = blockIdx.x * blockDim.x + threadIdx.x;
    if (idx >= npairs) return;
    int half_ = cols >> 1;
    int row = idx / half_;
    int cp = idx - row * half_;
    int h = cp >> 6;
    int d = cp & 63;
    int c0 = h * 128 + d;
    int p = pos_ids[row];
    float sn = stab[p * 64 + d];
    float cs = ctab[p * 64 + d];
    __half* rowp = T + (size_t)row * cols;
    float x0 = __half2float(rowp[c0]);
    float x1 = __half2float(rowp[c0 + 64]);
    rowp[c0]      = __float2half_rn(x0 * cs - x1 * sn);
    rowp[c0 + 64] = __float2half_rn(x1 * cs + x0 * sn);
}

// fast exp2 on the fma/alu pipes
__device__ __forceinline__ float exp2p(float x) {
    x = fmaxf(x, -126.f);
    float t = x + 12582912.f;
    float n = t - 12582912.f;
    float f = x - n;
    float p = 1.5403530e-4f;
    p = fmaf(p, f, 1.3333558e-3f);
    p = fmaf(p, f, 9.6181291e-3f);
    p = fmaf(p, f, 5.5504109e-2f);
    p = fmaf(p, f, 2.4022651e-1f);
    p = fmaf(p, f, 6.9314718e-1f);
    p = fmaf(p, f, 1.0f);
    float sc = __int_as_float(0x3f800000 + (__float_as_int(t) << 23));
    return p * sc;
}

__device__ __forceinline__ void mma_f16(float* c, uint32_t a0, uint32_t a1,
                                        uint32_t a2, uint32_t a3,
                                        uint32_t b0, uint32_t b1)
{
    asm volatile(
        "mma.sync.aligned.m16n8k16.row.col.f32.f16.f16.f32 "
        "{%0,%1,%2,%3}, {%4,%5,%6,%7}, {%8,%9}, {%0,%1,%2,%3};\n"
        : "+f"(c[0]), "+f"(c[1]), "+f"(c[2]), "+f"(c[3])
        : "r"(a0), "r"(a1), "r"(a2), "r"(a3), "r"(b0), "r"(b1));
}

__device__ __forceinline__ void ldsm4(uint32_t* r, uint32_t addr) {
    asm volatile("ldmatrix.sync.aligned.m8n8.x4.shared.b16 {%0,%1,%2,%3}, [%4];"
                 : "=r"(r[0]), "=r"(r[1]), "=r"(r[2]), "=r"(r[3]) : "r"(addr));
}

__device__ __forceinline__ void cp16(uint32_t dst, const void* src) {
    asm volatile("cp.async.cg.shared.global [%0], [%1], 16;\n"
                 :: "r"(dst), "l"(src));
}
#define CP_COMMIT() asm volatile("cp.async.commit_group;\n" ::: "memory")
#define CP_WAIT1()  asm volatile("cp.async.wait_group 1;\n" ::: "memory")
#define CP_WAIT0()  asm volatile("cp.async.wait_group 0;\n" ::: "memory")

// ---------------------------------------------------------------------------
// FP16 tensor-core GEMM: 128x128x64 tile, 128 threads (2x2 warps),
// 2 CTAs/SM, 3-stage cp.async ring with ONE barrier per k-chunk.
// ---------------------------------------------------------------------------
#define BM 128
#define BN 128
#define BK 64
#define GST2 72
#define GSTAGE (BM * GST2 * 2)           // 18432 B per tile stage
#define GSTG 3
#define GEMM_SMEM (2 * GSTG * GSTAGE)    // 110592 B

__global__ void __launch_bounds__(128, 2)
gemm16qkv(const __half* __restrict__ A, const __half* __restrict__ Bt,
          __half* __restrict__ Cq, __half* __restrict__ Ck,
          __half* __restrict__ Cv)
{
    extern __shared__ char smc[];
    const int tid  = threadIdx.x;
    const int warp = tid >> 5;
    const int lane = tid & 31;
    const int wm = warp >> 1;
    const int wn = warp & 1;
    const int g  = lane >> 2;
    const int tg = lane & 3;
    const int bm = blockIdx.y * BM;
    const int bn = blockIdx.x * BN;
    const int K = HID;

    const uint32_t sA = (uint32_t)__cvta_generic_to_shared(smc);
    const uint32_t sB = sA + GSTG * GSTAGE;
    const uint32_t aoff = ((((lane & 7) + ((lane >> 3) & 1) * 8)) * GST2 +
                           (lane >> 4) * 8) * 2;
    const uint32_t boff = ((((lane & 7) + (lane >> 4) * 8)) * GST2 +
                           ((lane >> 3) & 1) * 8) * 2;

    float acc[4][8][4];
#pragma unroll
    for (int mi = 0; mi < 4; mi++)
#pragma unroll
        for (int ni = 0; ni < 8; ni++)
#pragma unroll
            for (int r = 0; r < 4; r++) acc[mi][ni][r] = 0.f;

    const int T = K / BK;

    auto issue = [&](int t, int s) {
        const __half* Ag = A + (size_t)bm * K + t * BK;
#pragma unroll
        for (int u = 0; u < 8; u++) {
            int i = tid + 128 * u;
            int r = i >> 3, c8 = i & 7;
            cp16(sA + s * GSTAGE + (r * GST2 + c8 * 8) * 2,
                 Ag + (size_t)r * K + c8 * 8);
        }
        const __half* Bg = Bt + (size_t)bn * K + t * BK;
#pragma unroll
        for (int u = 0; u < 8; u++) {
            int i = tid + 128 * u;
            int r = i >> 3, c8 = i & 7;
            cp16(sB + s * GSTAGE + (r * GST2 + c8 * 8) * 2,
                 Bg + (size_t)r * K + c8 * 8);
        }
        CP_COMMIT();
    };

    issue(0, 0);
    issue(1, 1);

    for (int t = 0; t < T; t++) {
        if (t + 1 < T) CP_WAIT1(); else CP_WAIT0();
        __syncthreads();
        if (t + 2 < T) issue(t + 2, (t + 2) % GSTG);

        const int s = t % GSTG;
        const uint32_t Ab = sA + s * GSTAGE;
        const uint32_t Bb = sB + s * GSTAGE;

#pragma unroll
        for (int ks = 0; ks < 4; ks++) {
            uint32_t a[4][4], b[4][4];
#pragma unroll
            for (int mi = 0; mi < 4; mi++)
                ldsm4(a[mi], Ab + ((wm * 64 + mi * 16) * GST2 + ks * 16) * 2 + aoff);
#pragma unroll
            for (int ni2 = 0; ni2 < 4; ni2++)
                ldsm4(b[ni2], Bb + ((wn * 64 + ni2 * 16) * GST2 + ks * 16) * 2 + boff);
#pragma unroll
            for (int mi = 0; mi < 4; mi++)
#pragma unroll
                for (int ni = 0; ni < 8; ni++)
                    mma_f16(acc[mi][ni], a[mi][0], a[mi][1], a[mi][2], a[mi][3],
                            b[ni >> 1][(ni & 1) * 2], b[ni >> 1][(ni & 1) * 2 + 1]);
        }
    }

    __half* Co; int Nout; int colb;
    if (bn < HID)             { Co = Cq; Nout = HID; colb = bn; }
    else if (bn < HID + KVW)  { Co = Ck; Nout = KVW; colb = bn - HID; }
    else                      { Co = Cv; Nout = KVW; colb = bn - HID - KVW; }

#pragma unroll
    for (int mi = 0; mi < 4; mi++) {
        int row0 = bm + wm * 64 + mi * 16 + g;
#pragma unroll
        for (int ni = 0; ni < 8; ni++) {
            int col = colb + wn * 64 + ni * 8 + tg * 2;
            *(__half2*)(Co + (size_t)row0 * Nout + col) =
                __floats2half2_rn(acc[mi][ni][0], acc[mi][ni][1]);
            *(__half2*)(Co + (size_t)(row0 + 8) * Nout + col) =
                __floats2half2_rn(acc[mi][ni][2], acc[mi][ni][3]);
        }
    }
}

__global__ void __launch_bounds__(128, 2)
gemm16f(const __half* __restrict__ A, const __half* __restrict__ Bt,
        float* __restrict__ C, int M, int N, int K)
{
    extern __shared__ char smc[];
    const int tid  = threadIdx.x;
    const int warp = tid >> 5;
    const int lane = tid & 31;
    const int wm = warp >> 1;
    const int wn = warp & 1;
    const int g  = lane >> 2;
    const int tg = lane & 3;
    const int bm = blockIdx.y * BM;
    const int bn = blockIdx.x * BN;

    const uint32_t sA = (uint32_t)__cvta_generic_to_shared(smc);
    const uint32_t sB = sA + GSTG * GSTAGE;
    const uint32_t aoff = ((((lane & 7) + ((lane >> 3) & 1) * 8)) * GST2 +
                           (lane >> 4) * 8) * 2;
    const uint32_t boff = ((((lane & 7) + (lane >> 4) * 8)) * GST2 +
                           ((lane >> 3) & 1) * 8) * 2;

    float acc[4][8][4];
#pragma unroll
    for (int mi = 0; mi < 4; mi++)
#pragma unroll
        for (int ni = 0; ni < 8; ni++)
#pragma unroll
            for (int r = 0; r < 4; r++) acc[mi][ni][r] = 0.f;

    const int T = K / BK;

    auto issue = [&](int t, int s) {
        const __half* Ag = A + (size_t)bm * K + t * BK;
#pragma unroll
        for (int u = 0; u < 8; u++) {
            int i = tid + 128 * u;
            int r = i >> 3, c8 = i & 7;
            cp16(sA + s * GSTAGE + (r * GST2 + c8 * 8) * 2,
                 Ag + (size_t)r * K + c8 * 8);
        }
        const __half* Bg = Bt + (size_t)bn * K + t * BK;
#pragma unroll
        for (int u = 0; u < 8; u++) {
            int i = tid + 128 * u;
            int r = i >> 3, c8 = i & 7;
            cp16(sB + s * GSTAGE + (r * GST2 + c8 * 8) * 2,
                 Bg + (size_t)r * K + c8 * 8);
        }
        CP_COMMIT();
    };

    issue(0, 0);
    issue(1, 1);

    for (int t = 0; t < T; t++) {
        if (t + 1 < T) CP_WAIT1(); else CP_WAIT0();
        __syncthreads();
        if (t + 2 < T) issue(t + 2, (t + 2) % GSTG);

        const int s = t % GSTG;
        const uint32_t Ab = sA + s * GSTAGE;
        const uint32_t Bb = sB + s * GSTAGE;

#pragma unroll
        for (int ks = 0; ks < 4; ks++) {
            uint32_t a[4][4], b[4][4];
#pragma unroll
            for (int mi = 0; mi < 4; mi++)
                ldsm4(a[mi], Ab + ((wm * 64 + mi * 16) * GST2 + ks * 16) * 2 + aoff);
#pragma unroll
            for (int ni2 = 0; ni2 < 4; ni2++)
                ldsm4(b[ni2], Bb + ((wn * 64 + ni2 * 16) * GST2 + ks * 16) * 2 + boff);
#pragma unroll
            for (int mi = 0; mi < 4; mi++)
#pragma unroll
                for (int ni = 0; ni < 8; ni++)
                    mma_f16(acc[mi][ni], a[mi][0], a[mi][1], a[mi][2], a[mi][3],
                            b[ni >> 1][(ni & 1) * 2], b[ni >> 1][(ni & 1) * 2 + 1]);
        }
    }

#pragma unroll
    for (int mi = 0; mi < 4; mi++) {
        int row0 = bm + wm * 64 + mi * 16 + g;
#pragma unroll
        for (int ni = 0; ni < 8; ni++) {
            int col = bn + wn * 64 + ni * 8 + tg * 2;
            *(float2*)(C + (size_t)row0 * N + col) =
                make_float2(acc[mi][ni][0], acc[mi][ni][1]);
            *(float2*)(C + (size_t)(row0 + 8) * N + col) =
                make_float2(acc[mi][ni][2], acc[mi][ni][3]);
        }
    }
}

// ---------------------------------------------------------------------------
// FP16 tensor-core flash attention (round-11/13 best config):
// CTA = 128 q rows x head x batch; 8 warps x 16 rows; K-tile 64, 2-stage.
// ---------------------------------------------------------------------------
#define FQ   128
#define FKT  64
#define QST2 136
#define KST2 136
#define VST2 72
#define PST2 72

#define KSTAGE (FKT * KST2 * 2)
#define VSTAGE (128 * VST2 * 2)
#define OFF_K  0
#define OFF_V  (2 * KSTAGE)
#define OFF_QP (OFF_V + 2 * VSTAGE)
#define OFF_M  (OFF_QP + FQ * QST2 * 2)
#define FL_SMEM (OFF_M + 2 * FKT * 4)    // 107008 B

#define SCL 0.12751743f   // (1/sqrt(128)) * log2(e)

__global__ void __launch_bounds__(256, 1)
flash16(const __half* __restrict__ Q, const __half* __restrict__ K,
        const __half* __restrict__ Vt, const float* __restrict__ amask,
        __half* __restrict__ Oc)
{
    extern __shared__ char smc[];
    float* kmb = (float*)(smc + OFF_M);
    const uint32_t sbase = (uint32_t)__cvta_generic_to_shared(smc);

    const int hb = blockIdx.x;
    const int h = hb & 31, b = hb >> 5;
    const int qb = gridDim.y - 1 - blockIdx.y;
    const int q0 = qb * FQ;
    const int tid = threadIdx.x;
    const int w = tid >> 5, lane = tid & 31;
    const int g = lane >> 2, tg = lane & 3;
    const int kvh = h >> 2;
    const int myrowmax = q0 + w * 16 + 15;
    const int w16 = w * 16;

    const uint32_t aoffP = ((((lane & 7) + ((lane >> 3) & 1) * 8)) * PST2 +
                            (lane >> 4) * 8) * 2;
    const uint32_t boffK = ((((lane & 7) + (lane >> 4) * 8)) * KST2 +
                            ((lane >> 3) & 1) * 8) * 2;
    const uint32_t boffV = ((((lane & 7) + (lane >> 4) * 8)) * VST2 +
                            ((lane >> 3) & 1) * 8) * 2;

    float oacc[16][4];
#pragma unroll
    for (int nt = 0; nt < 16; nt++)
#pragma unroll
        for (int r = 0; r < 4; r++) oacc[nt][r] = 0.f;
    float m2[2] = {-1e9f, -1e9f}, l2[2] = {0.f, 0.f};

    auto issue = [&](int t, int s) {
        const __half* Kg = K + (size_t)(b * SEQ + t * FKT) * KVW + kvh * HD;
        uint32_t Ksb = sbase + OFF_K + s * KSTAGE;
#pragma unroll
        for (int u = 0; u < 4; u++) {
            int i = tid + 256 * u;
            int r = i >> 4, c8 = i & 15;
            cp16(Ksb + (r * KST2 + c8 * 8) * 2, Kg + (size_t)r * KVW + c8 * 8);
        }
        const __half* Vg = Vt + ((size_t)(b * 8 + kvh) * 128) * SEQ + t * FKT;
        uint32_t Vsb = sbase + OFF_V + s * VSTAGE;
#pragma unroll
        for (int u = 0; u < 4; u++) {
            int i = tid + 256 * u;
            int r = i >> 3, c8 = i & 7;
            cp16(Vsb + (r * VST2 + c8 * 8) * 2, Vg + (size_t)r * SEQ + c8 * 8);
        }
        if (tid < FKT)
            kmb[s * FKT + tid] =
                (amask[b * SEQ + t * FKT + tid] > 0.f) ? 0.f : -1e9f;
        CP_COMMIT();
    };

    issue(0, 0);

    // Q tile -> smem
    {
        const __half* Qg = Q + (size_t)(b * SEQ + q0) * HID + h * HD;
        __half* Qs = (__half*)(smc + OFF_QP);
#pragma unroll
        for (int u = 0; u < 8; u++) {
            int i = tid + 256 * u;
            int r = i >> 4, c8 = i & 15;
            float4 v = *(const float4*)(Qg + (size_t)r * HID + c8 * 8);
            *(float4*)(Qs + r * QST2 + c8 * 8) = v;
        }
    }
    __syncthreads();

    // Q fragments -> registers (32 regs)
    uint32_t qa[8][4];
    {
        const uint32_t* Qw = (const uint32_t*)(smc + OFF_QP);
#pragma unroll
        for (int ks = 0; ks < 8; ks++) {
            const int kw = ks * 8;
            qa[ks][0] = Qw[(w16 + g) * 68 + kw + tg];
            qa[ks][1] = Qw[(w16 + g + 8) * 68 + kw + tg];
            qa[ks][2] = Qw[(w16 + g) * 68 + kw + 4 + tg];
            qa[ks][3] = Qw[(w16 + g + 8) * 68 + kw + 4 + tg];
        }
    }
    __syncthreads();   // Q reads done -> region becomes P

    const int T = 2 * (qb + 1);
    const uint32_t Pbase = sbase + OFF_QP + (w16 * PST2) * 2;

    for (int t = 0; t < T; t++) {
        const int buf = t & 1;
        if (t + 1 < T) {
            issue(t + 1, buf ^ 1);
            CP_WAIT1();
        } else {
            CP_WAIT0();
        }
        __syncthreads();

        const int k0 = t * FKT;
        if (k0 <= myrowmax) {

            // ---- S = Q @ K^T (16 x 64 per warp) ----
            float sacc[8][4];
#pragma unroll
            for (int nt = 0; nt < 8; nt++)
#pragma unroll
                for (int r = 0; r < 4; r++) sacc[nt][r] = 0.f;

            const uint32_t Kb = sbase + OFF_K + buf * KSTAGE;
#pragma unroll
            for (int ks = 0; ks < 8; ks++) {
#pragma unroll
                for (int nt2 = 0; nt2 < 4; nt2++) {
                    uint32_t kb[4];
                    ldsm4(kb, Kb + (nt2 * 16 * KST2 + ks * 16) * 2 + boffK);
                    mma_f16(sacc[nt2 * 2], qa[ks][0], qa[ks][1], qa[ks][2],
                            qa[ks][3], kb[0], kb[1]);
                    mma_f16(sacc[nt2 * 2 + 1], qa[ks][0], qa[ks][1], qa[ks][2],
                            qa[ks][3], kb[2], kb[3]);
                }
            }

            // ---- mask + scale into exp2 domain ----
            const int rowg0 = q0 + w16 + g;
            const int rowg1 = rowg0 + 8;
#pragma unroll
            for (int nt = 0; nt < 8; nt++) {
                int cl = nt * 8 + 2 * tg;
                int c0 = k0 + cl;
                float kb0 = kmb[buf * FKT + cl];
                float kb1 = kmb[buf * FKT + cl + 1];
                sacc[nt][0] = (c0     <= rowg0) ? sacc[nt][0] * SCL + kb0 : -1e9f;
                sacc[nt][1] = (c0 + 1 <= rowg0) ? sacc[nt][1] * SCL + kb1 : -1e9f;
                sacc[nt][2] = (c0     <= rowg1) ? sacc[nt][2] * SCL + kb0 : -1e9f;
                sacc[nt][3] = (c0 + 1 <= rowg1) ? sacc[nt][3] * SCL + kb1 : -1e9f;
            }

            // ---- online softmax (exp2 domain), P -> fp16 smem ----
            __half2* Ph = (__half2*)(smc + OFF_QP);
#pragma unroll
            for (int r = 0; r < 2; r++) {
                float pm = -1e30f;
#pragma unroll
                for (int nt = 0; nt < 8; nt++)
                    pm = fmaxf(pm, fmaxf(sacc[nt][2 * r], sacc[nt][2 * r + 1]));
                pm = fmaxf(pm, __shfl_xor_sync(0xffffffffu, pm, 1));
                pm = fmaxf(pm, __shfl_xor_sync(0xffffffffu, pm, 2));
                float mn = fmaxf(m2[r], pm);
                float al = exp2p(m2[r] - mn);
                m2[r] = mn;
                float rs = 0.f;
                __half2* prow = Ph + (w16 + g + 8 * r) * 36;
#pragma unroll
                for (int nt = 0; nt < 8; nt++) {
                    float p0 = exp2p(sacc[nt][2 * r] - mn);
                    float p1 = exp2p(sacc[nt][2 * r + 1] - mn);
                    rs += p0 + p1;
                    prow[nt * 4 + tg] = __floats2half2_rn(p0, p1);
                }
                rs += __shfl_xor_sync(0xffffffffu, rs, 1);
                rs += __shfl_xor_sync(0xffffffffu, rs, 2);
                l2[r] = l2[r] * al + rs;
                if (al != 1.f) {
#pragma unroll
                    for (int nt = 0; nt < 16; nt++) {
                        oacc[nt][2 * r]     *= al;
                        oacc[nt][2 * r + 1] *= al;
                    }
                }
            }
            __syncwarp();

            // ---- O += P @ V ----
            const uint32_t Vb = sbase + OFF_V + buf * VSTAGE;
#pragma unroll
            for (int ks = 0; ks < 4; ks++) {
                uint32_t pa[4];
                ldsm4(pa, Pbase + (ks * 16) * 2 + aoffP);
#pragma unroll
                for (int nt2 = 0; nt2 < 8; nt2++) {
                    uint32_t vb[4];
                    ldsm4(vb, Vb + (nt2 * 16 * VST2 + ks * 16) * 2 + boffV);
                    mma_f16(oacc[nt2 * 2], pa[0], pa[1], pa[2], pa[3],
                            vb[0], vb[1]);
                    mma_f16(oacc[nt2 * 2 + 1], pa[0], pa[1], pa[2], pa[3],
                            vb[2], vb[3]);
                }
            }
        }
        __syncthreads();
    }

    // ---- epilogue: normalize + fp16 store to A ----
    float i0 = 1.f / l2[0], i1 = 1.f / l2[1];
    __half* Ar0 = Oc + (size_t)(b * SEQ + q0 + w16 + g) * HID + h * HD;
    __half* Ar1 = Ar0 + (size_t)8 * HID;
#pragma unroll
    for (int nt = 0; nt < 16; nt++) {
        int c = nt * 8 + 2 * tg;
        *(__half2*)(Ar0 + c) = __floats2half2_rn(oacc[nt][0] * i0,
                                                 oacc[nt][1] * i0);
        *(__half2*)(Ar1 + c) = __floats2half2_rn(oacc[nt][2] * i1,
                                                 oacc[nt][3] * i1);
    }
}

// ---------------------------------------------------------------------------
// Launch
// ---------------------------------------------------------------------------
extern "C" void kernel_launch(void* const* d_in, const int* in_sizes, int n_in,
                              void* d_out, int out_size)
{
    const float* hs    = (const float*)d_in[0];
    const float* amask = (const float*)d_in[1];
    const int*   pos   = (const int*)d_in[2];
    const float* Wq    = (const float*)d_in[3];
    const float* Wk    = (const float*)d_in[4];
    const float* Wv    = (const float*)d_in[5];
    const float* Wo    = (const float*)d_in[6];
    float* out = (float*)d_out;

    __half *Xp, *Wqkvp, *Wop, *Qp, *Kp, *Vp, *Vtp, *Ap;
    float *sinp, *cosp;
    cudaGetSymbolAddress((void**)&Xp,    g_X);
    cudaGetSymbolAddress((void**)&Wqkvp, g_Wqkv);
    cudaGetSymbolAddress((void**)&Wop,   g_Wo);
    cudaGetSymbolAddress((void**)&Qp,    g_Q);
    cudaGetSymbolAddress((void**)&Kp,    g_K);
    cudaGetSymbolAddress((void**)&Vp,    g_V);
    cudaGetSymbolAddress((void**)&Vtp,   g_Vt);
    cudaGetSymbolAddress((void**)&Ap,    g_A);
    cudaGetSymbolAddress((void**)&sinp,  g_sin);
    cudaGetSymbolAddress((void**)&cosp,  g_cos);

    cudaFuncSetAttribute(gemm16qkv, cudaFuncAttributeMaxDynamicSharedMemorySize,
                         GEMM_SMEM);
    cudaFuncSetAttribute(gemm16f, cudaFuncAttributeMaxDynamicSharedMemorySize,
                         GEMM_SMEM);
    cudaFuncSetAttribute(flash16, cudaFuncAttributeMaxDynamicSharedMemorySize,
                         FL_SMEM);

    // Convert X; transpose+convert weights; build RoPE table
    {
        int n = MROWS * HID / 4;
        f2h_kernel<<<(n + 255) / 256, 256>>>(hs, Xp, n);
        dim3 blk(32, 8);
        transpose_all<<<dim3(HID / 32, HID / 32, 4), blk>>>(Wq, Wk, Wv, Wo,
                                                            Wqkvp, Wop);
        int nt = MAXPOS * 64;
        rope_table_kernel<<<(nt + 255) / 256, 256>>>(sinp, cosp);
    }

    // Fused QKV projection
    gemm16qkv<<<dim3(NQKV / BN, MROWS / BM), 128, GEMM_SMEM>>>(Xp, Wqkvp,
                                                               Qp, Kp, Vp);

    // RoPE on Q and K (table-driven)
    {
        int npq = MROWS * (HID / 2);
        rope_h<<<(npq + 255) / 256, 256>>>(Qp, pos, sinp, cosp, HID, npq);
        int npk = MROWS * (KVW / 2);
        rope_h<<<(npk + 255) / 256, 256>>>(Kp, pos, sinp, cosp, KVW, npk);
    }

    // Transpose V for the PV matmul
    {
        dim3 blk(32, 8);
        vtrans_kernel<<<dim3(SEQ / 32, 128 / 32, 16), blk>>>(Vp, Vtp);
    }

    // FP16 tensor-core flash attention
    flash16<<<dim3(NHEADS * BATCH, SEQ / FQ), 256, FL_SMEM>>>(Qp, Kp, Vtp,
                                                              amask, Ap);

    // Output projection, fp32 output
    gemm16f<<<dim3(HID / BN, MROWS / BM), 128, GEMM_SMEM>>>(Ap, Wop, out,
                                                            MROWS, HID, HID);
}

// round 16
// speedup vs baseline: 1.0483x; 1.0483x over previous
#include <cuda_runtime.h>
#include <cuda_fp16.h>
#include <math.h>
#include <stdint.h>

// ---------------------------------------------------------------------------
// Problem constants
// ---------------------------------------------------------------------------
#define HID    4096
#define SEQ    2048
#define BATCH  2
#define NHEADS 32
#define NKV    8
#define HD     128
#define KVW    (NKV * HD)        // 1024
#define MROWS  (BATCH * SEQ)     // 4096
#define NQKV   (HID + 2 * KVW)   // 6144
#define MAXPOS 4096

// ---------------------------------------------------------------------------
// Scratch (device globals: no allocation allowed) — fp16 operands
// ---------------------------------------------------------------------------
__device__ __half g_X   [(size_t)MROWS * HID];
__device__ __half g_Wqkv[(size_t)NQKV * HID];   // [n][k] transposed weights
__device__ __half g_Wo  [(size_t)HID * HID];
__device__ __half g_Q   [(size_t)MROWS * HID];
__device__ __half g_K   [(size_t)MROWS * KVW];
__device__ __half g_V   [(size_t)MROWS * KVW];
__device__ __half g_Vt  [(size_t)MROWS * KVW];  // [b*8+kvh][d][seq]
__device__ __half g_A   [(size_t)MROWS * HID];
__device__ float  g_sin [MAXPOS * 64];
__device__ float  g_cos [MAXPOS * 64];

// ---------------------------------------------------------------------------
// helpers
// ---------------------------------------------------------------------------
__global__ void f2h_kernel(const float* __restrict__ in,
                           __half* __restrict__ out, int n4)
{
    int i = blockIdx.x * blockDim.x + threadIdx.x;
    if (i >= n4) return;
    float4 v = ((const float4*)in)[i];
    __half2* o = (__half2*)(out + 4 * (size_t)i);
    o[0] = __floats2half2_rn(v.x, v.y);
    o[1] = __floats2half2_rn(v.z, v.w);
}

// fused transpose + convert of all 4 weight matrices (z selects matrix)
__global__ void transpose_all(const float* __restrict__ Wq,
                              const float* __restrict__ Wk,
                              const float* __restrict__ Wv,
                              const float* __restrict__ Wo,
                              __half* __restrict__ Wqkv,
                              __half* __restrict__ Woh)
{
    __shared__ float t[32][33];
    const int z = blockIdx.z;
    const float* in; __half* out; int N;
    if (z == 0)      { in = Wq; out = Wqkv;                              N = HID; }
    else if (z == 1) { in = Wk; out = Wqkv + (size_t)HID * HID;          N = KVW; }
    else if (z == 2) { in = Wv; out = Wqkv + (size_t)(HID + KVW) * HID;  N = KVW; }
    else             { in = Wo; out = Woh;                               N = HID; }
    int n0 = blockIdx.x * 32;
    if (n0 >= N) return;
    int k0 = blockIdx.y * 32;
    int x = threadIdx.x, y = threadIdx.y;   // 32 x 8
#pragma unroll
    for (int i = 0; i < 32; i += 8)
        t[y + i][x] = in[(size_t)(k0 + y + i) * N + n0 + x];
    __syncthreads();
#pragma unroll
    for (int i = 0; i < 32; i += 8)
        out[(size_t)(n0 + y + i) * HID + k0 + x] = __float2half_rn(t[x][y + i]);
}

// V transpose: Vt[b*8+kvh][d][s] = V[(b*SEQ+s)][kvh*128+d]
__global__ void vtrans_kernel(const __half* __restrict__ V,
                              __half* __restrict__ Vt)
{
    __shared__ __half t[32][33];
    int p = blockIdx.z;
    int b = p >> 3, kvh = p & 7;
    int s0 = blockIdx.x * 32, d0 = blockIdx.y * 32;
    int x = threadIdx.x, y = threadIdx.y;
#pragma unroll
    for (int i = 0; i < 32; i += 8)
        t[y + i][x] = V[(size_t)(b * SEQ + s0 + y + i) * KVW + kvh * 128 + d0 + x];
    __syncthreads();
#pragma unroll
    for (int i = 0; i < 32; i += 8)
        Vt[((size_t)p * 128 + d0 + y + i) * SEQ + s0 + x] = t[x][y + i];
}

// RoPE sin/cos table build (bit-identical math to per-element path)
__global__ void rope_table_kernel(float* __restrict__ stab,
                                  float* __restrict__ ctab)
{
    int i = blockIdx.x * blockDim.x + threadIdx.x;
    if (i >= MAXPOS * 64) return;
    int p = i >> 6, d = i & 63;
    double inv = pow(10000.0, -((double)d) / 64.0);
    float ang = (float)((double)p * inv);
    stab[i] = sinf(ang);
    ctab[i] = cosf(ang);
}

// RoPE apply (in-place on fp16, pair-safe), table-driven.
__global__ void rope_h(__half* __restrict__ T, const int* __restrict__ pos_ids,
                       const float* __restrict__ stab,
                       const float* __restrict__ ctab,
                       int cols, int npairs)
{
    int idx = blockIdx.x * blockDim.x + threadIdx.x;
    if (idx >= npairs) return;
    int half_ = cols >> 1;
    int row = idx / half_;
    int cp = idx - row * half_;
    int h = cp >> 6;
    int d = cp & 63;
    int c0 = h * 128 + d;
    int p = pos_ids[row];
    float sn = stab[p * 64 + d];
    float cs = ctab[p * 64 + d];
    __half* rowp = T + (size_t)row * cols;
    float x0 = __half2float(rowp[c0]);
    float x1 = __half2float(rowp[c0 + 64]);
    rowp[c0]      = __float2half_rn(x0 * cs - x1 * sn);
    rowp[c0 + 64] = __float2half_rn(x1 * cs + x0 * sn);
}

// fast exp2 on the fma/alu pipes
__device__ __forceinline__ float exp2p(float x) {
    x = fmaxf(x, -126.f);
    float t = x + 12582912.f;
    float n = t - 12582912.f;
    float f = x - n;
    float p = 1.5403530e-4f;
    p = fmaf(p, f, 1.3333558e-3f);
    p = fmaf(p, f, 9.6181291e-3f);
    p = fmaf(p, f, 5.5504109e-2f);
    p = fmaf(p, f, 2.4022651e-1f);
    p = fmaf(p, f, 6.9314718e-1f);
    p = fmaf(p, f, 1.0f);
    float sc = __int_as_float(0x3f800000 + (__float_as_int(t) << 23));
    return p * sc;
}

__device__ __forceinline__ void mma_f16(float* c, uint32_t a0, uint32_t a1,
                                        uint32_t a2, uint32_t a3,
                                        uint32_t b0, uint32_t b1)
{
    asm volatile(
        "mma.sync.aligned.m16n8k16.row.col.f32.f16.f16.f32 "
        "{%0,%1,%2,%3}, {%4,%5,%6,%7}, {%8,%9}, {%0,%1,%2,%3};\n"
        : "+f"(c[0]), "+f"(c[1]), "+f"(c[2]), "+f"(c[3])
        : "r"(a0), "r"(a1), "r"(a2), "r"(a3), "r"(b0), "r"(b1));
}

__device__ __forceinline__ void ldsm4(uint32_t* r, uint32_t addr) {
    asm volatile("ldmatrix.sync.aligned.m8n8.x4.shared.b16 {%0,%1,%2,%3}, [%4];"
                 : "=r"(r[0]), "=r"(r[1]), "=r"(r[2]), "=r"(r[3]) : "r"(addr));
}

__device__ __forceinline__ void cp16(uint32_t dst, const void* src) {
    asm volatile("cp.async.cg.shared.global [%0], [%1], 16;\n"
                 :: "r"(dst), "l"(src));
}
#define CP_COMMIT() asm volatile("cp.async.commit_group;\n" ::: "memory")
#define CP_WAIT1()  asm volatile("cp.async.wait_group 1;\n" ::: "memory")
#define CP_WAIT0()  asm volatile("cp.async.wait_group 0;\n" ::: "memory")

// ---------------------------------------------------------------------------
// FP16 tensor-core GEMM: 128x128x64 tile, 256 threads (2x4 warps, 64x32
// warp tile -> 64 acc regs, no spills), 2 CTAs/SM, 2-stage cp.async.
// ---------------------------------------------------------------------------
#define BM 128
#define BN 128
#define BK 64
#define GST2 72
#define GSTAGE (BM * GST2 * 2)           // 18432 B per tile stage
#define GEMM_SMEM (4 * GSTAGE)           // 73728 B

// shared GEMM body: computes acc for this thread's warp tile
#define GEMM_BODY(KDIM)                                                        \
    const int tid  = threadIdx.x;                                              \
    const int warp = tid >> 5;                                                 \
    const int lane = tid & 31;                                                 \
    const int wm = warp >> 2;              /* 0..1: 64-row slab  */            \
    const int wn = warp & 3;               /* 0..3: 32-col slab  */            \
    const int g  = lane >> 2;                                                  \
    const int tg = lane & 3;                                                   \
    const uint32_t sA = (uint32_t)__cvta_generic_to_shared(smc);               \
    const uint32_t sB = sA + 2 * GSTAGE;                                       \
    const uint32_t aoff = ((((lane & 7) + ((lane >> 3) & 1) * 8)) * GST2 +     \
                           (lane >> 4) * 8) * 2;                               \
    const uint32_t boff = ((((lane & 7) + (lane >> 4) * 8)) * GST2 +           \
                           ((lane >> 3) & 1) * 8) * 2;                         \
    float acc[4][4][4];                                                        \
    _Pragma("unroll")                                                          \
    for (int mi = 0; mi < 4; mi++)                                             \
        _Pragma("unroll")                                                      \
        for (int ni = 0; ni < 4; ni++)                                         \
            _Pragma("unroll")                                                  \
            for (int r = 0; r < 4; r++) acc[mi][ni][r] = 0.f;                  \
    const int T = (KDIM) / BK;                                                 \
    auto issue = [&](int t, int s) {                                           \
        const __half* Ag = A + (size_t)bm * (KDIM) + t * BK;                   \
        _Pragma("unroll")                                                      \
        for (int u = 0; u < 4; u++) {                                          \
            int i = tid + 256 * u;                                             \
            int r = i >> 3, c8 = i & 7;                                        \
            cp16(sA + s * GSTAGE + (r * GST2 + c8 * 8) * 2,                    \
                 Ag + (size_t)r * (KDIM) + c8 * 8);                            \
        }                                                                      \
        const __half* Bg = Bt + (size_t)bn * (KDIM) + t * BK;                  \
        _Pragma("unroll")                                                      \
        for (int u = 0; u < 4; u++) {                                          \
            int i = tid + 256 * u;                                             \
            int r = i >> 3, c8 = i & 7;                                        \
            cp16(sB + s * GSTAGE + (r * GST2 + c8 * 8) * 2,                    \
                 Bg + (size_t)r * (KDIM) + c8 * 8);                            \
        }                                                                      \
        CP_COMMIT();                                                           \
    };                                                                         \
    issue(0, 0);                                                               \
    int buf = 0;                                                               \
    for (int t = 0; t < T; t++) {                                              \
        if (t + 1 < T) { issue(t + 1, buf ^ 1); CP_WAIT1(); }                  \
        else           { CP_WAIT0(); }                                         \
        __syncthreads();                                                       \
        const uint32_t Ab = sA + buf * GSTAGE;                                 \
        const uint32_t Bb = sB + buf * GSTAGE;                                 \
        _Pragma("unroll")                                                      \
        for (int ks = 0; ks < 4; ks++) {                                       \
            uint32_t a[4][4], b[2][4];                                         \
            _Pragma("unroll")                                                  \
            for (int mi = 0; mi < 4; mi++)                                     \
                ldsm4(a[mi], Ab + ((wm * 64 + mi * 16) * GST2 + ks * 16) * 2   \
                             + aoff);                                          \
            _Pragma("unroll")                                                  \
            for (int ni2 = 0; ni2 < 2; ni2++)                                  \
                ldsm4(b[ni2], Bb + ((wn * 32 + ni2 * 16) * GST2 + ks * 16) * 2 \
                              + boff);                                         \
            _Pragma("unroll")                                                  \
            for (int mi = 0; mi < 4; mi++)                                     \
                _Pragma("unroll")                                              \
                for (int ni = 0; ni < 4; ni++)                                 \
                    mma_f16(acc[mi][ni], a[mi][0], a[mi][1], a[mi][2],         \
                            a[mi][3], b[ni >> 1][(ni & 1) * 2],                \
                            b[ni >> 1][(ni & 1) * 2 + 1]);                     \
        }                                                                      \
        __syncthreads();                                                       \
        buf ^= 1;                                                              \
    }

__global__ void __launch_bounds__(256, 2)
gemm16qkv(const __half* __restrict__ A, const __half* __restrict__ Bt,
          __half* __restrict__ Cq, __half* __restrict__ Ck,
          __half* __restrict__ Cv)
{
    extern __shared__ char smc[];
    const int bm = blockIdx.y * BM;
    const int bn = blockIdx.x * BN;
    GEMM_BODY(HID)

    __half* Co; int Nout; int colb;
    if (bn < HID)             { Co = Cq; Nout = HID; colb = bn; }
    else if (bn < HID + KVW)  { Co = Ck; Nout = KVW; colb = bn - HID; }
    else                      { Co = Cv; Nout = KVW; colb = bn - HID - KVW; }

#pragma unroll
    for (int mi = 0; mi < 4; mi++) {
        int row0 = bm + wm * 64 + mi * 16 + g;
#pragma unroll
        for (int ni = 0; ni < 4; ni++) {
            int col = colb + wn * 32 + ni * 8 + tg * 2;
            *(__half2*)(Co + (size_t)row0 * Nout + col) =
                __floats2half2_rn(acc[mi][ni][0], acc[mi][ni][1]);
            *(__half2*)(Co + (size_t)(row0 + 8) * Nout + col) =
                __floats2half2_rn(acc[mi][ni][2], acc[mi][ni][3]);
        }
    }
}

__global__ void __launch_bounds__(256, 2)
gemm16f(const __half* __restrict__ A, const __half* __restrict__ Bt,
        float* __restrict__ C, int M, int N, int K)
{
    extern __shared__ char smc[];
    const int bm = blockIdx.y * BM;
    const int bn = blockIdx.x * BN;
    GEMM_BODY(K)

#pragma unroll
    for (int mi = 0; mi < 4; mi++) {
        int row0 = bm + wm * 64 + mi * 16 + g;
#pragma unroll
        for (int ni = 0; ni < 4; ni++) {
            int col = bn + wn * 32 + ni * 8 + tg * 2;
            *(float2*)(C + (size_t)row0 * N + col) =
                make_float2(acc[mi][ni][0], acc[mi][ni][1]);
            *(float2*)(C + (size_t)(row0 + 8) * N + col) =
                make_float2(acc[mi][ni][2], acc[mi][ni][3]);
        }
    }
}

// ---------------------------------------------------------------------------
// FP16 tensor-core flash attention (round-11/13 best config):
// CTA = 128 q rows x head x batch; 8 warps x 16 rows; K-tile 64, 2-stage.
// ---------------------------------------------------------------------------
#define FQ   128
#define FKT  64
#define QST2 136
#define KST2 136
#define VST2 72
#define PST2 72

#define KSTAGE (FKT * KST2 * 2)
#define VSTAGE (128 * VST2 * 2)
#define OFF_K  0
#define OFF_V  (2 * KSTAGE)
#define OFF_QP (OFF_V + 2 * VSTAGE)
#define OFF_M  (OFF_QP + FQ * QST2 * 2)
#define FL_SMEM (OFF_M + 2 * FKT * 4)    // 107008 B

#define SCL 0.12751743f   // (1/sqrt(128)) * log2(e)

__global__ void __launch_bounds__(256, 1)
flash16(const __half* __restrict__ Q, const __half* __restrict__ K,
        const __half* __restrict__ Vt, const float* __restrict__ amask,
        __half* __restrict__ Oc)
{
    extern __shared__ char smc[];
    float* kmb = (float*)(smc + OFF_M);
    const uint32_t sbase = (uint32_t)__cvta_generic_to_shared(smc);

    const int hb = blockIdx.x;
    const int h = hb & 31, b = hb >> 5;
    const int qb = gridDim.y - 1 - blockIdx.y;
    const int q0 = qb * FQ;
    const int tid = threadIdx.x;
    const int w = tid >> 5, lane = tid & 31;
    const int g = lane >> 2, tg = lane & 3;
    const int kvh = h >> 2;
    const int myrowmax = q0 + w * 16 + 15;
    const int w16 = w * 16;

    const uint32_t aoffP = ((((lane & 7) + ((lane >> 3) & 1) * 8)) * PST2 +
                            (lane >> 4) * 8) * 2;
    const uint32_t boffK = ((((lane & 7) + (lane >> 4) * 8)) * KST2 +
                            ((lane >> 3) & 1) * 8) * 2;
    const uint32_t boffV = ((((lane & 7) + (lane >> 4) * 8)) * VST2 +
                            ((lane >> 3) & 1) * 8) * 2;

    float oacc[16][4];
#pragma unroll
    for (int nt = 0; nt < 16; nt++)
#pragma unroll
        for (int r = 0; r < 4; r++) oacc[nt][r] = 0.f;
    float m2[2] = {-1e9f, -1e9f}, l2[2] = {0.f, 0.f};

    auto issue = [&](int t, int s) {
        const __half* Kg = K + (size_t)(b * SEQ + t * FKT) * KVW + kvh * HD;
        uint32_t Ksb = sbase + OFF_K + s * KSTAGE;
#pragma unroll
        for (int u = 0; u < 4; u++) {
            int i = tid + 256 * u;
            int r = i >> 4, c8 = i & 15;
            cp16(Ksb + (r * KST2 + c8 * 8) * 2, Kg + (size_t)r * KVW + c8 * 8);
        }
        const __half* Vg = Vt + ((size_t)(b * 8 + kvh) * 128) * SEQ + t * FKT;
        uint32_t Vsb = sbase + OFF_V + s * VSTAGE;
#pragma unroll
        for (int u = 0; u < 4; u++) {
            int i = tid + 256 * u;
            int r = i >> 3, c8 = i & 7;
            cp16(Vsb + (r * VST2 + c8 * 8) * 2, Vg + (size_t)r * SEQ + c8 * 8);
        }
        if (tid < FKT)
            kmb[s * FKT + tid] =
                (amask[b * SEQ + t * FKT + tid] > 0.f) ? 0.f : -1e9f;
        CP_COMMIT();
    };

    issue(0, 0);

    // Q tile -> smem
    {
        const __half* Qg = Q + (size_t)(b * SEQ + q0) * HID + h * HD;
        __half* Qs = (__half*)(smc + OFF_QP);
#pragma unroll
        for (int u = 0; u < 8; u++) {
            int i = tid + 256 * u;
            int r = i >> 4, c8 = i & 15;
            float4 v = *(const float4*)(Qg + (size_t)r * HID + c8 * 8);
            *(float4*)(Qs + r * QST2 + c8 * 8) = v;
        }
    }
    __syncthreads();

    // Q fragments -> registers (32 regs)
    uint32_t qa[8][4];
    {
        const uint32_t* Qw = (const uint32_t*)(smc + OFF_QP);
#pragma unroll
        for (int ks = 0; ks < 8; ks++) {
            const int kw = ks * 8;
            qa[ks][0] = Qw[(w16 + g) * 68 + kw + tg];
            qa[ks][1] = Qw[(w16 + g + 8) * 68 + kw + tg];
            qa[ks][2] = Qw[(w16 + g) * 68 + kw + 4 + tg];
            qa[ks][3] = Qw[(w16 + g + 8) * 68 + kw + 4 + tg];
        }
    }
    __syncthreads();   // Q reads done -> region becomes P

    const int T = 2 * (qb + 1);
    const uint32_t Pbase = sbase + OFF_QP + (w16 * PST2) * 2;

    for (int t = 0; t < T; t++) {
        const int buf = t & 1;
        if (t + 1 < T) {
            issue(t + 1, buf ^ 1);
            CP_WAIT1();
        } else {
            CP_WAIT0();
        }
        __syncthreads();

        const int k0 = t * FKT;
        if (k0 <= myrowmax) {

            // ---- S = Q @ K^T (16 x 64 per warp) ----
            float sacc[8][4];
#pragma unroll
            for (int nt = 0; nt < 8; nt++)
#pragma unroll
                for (int r = 0; r < 4; r++) sacc[nt][r] = 0.f;

            const uint32_t Kb = sbase + OFF_K + buf * KSTAGE;
#pragma unroll
            for (int ks = 0; ks < 8; ks++) {
#pragma unroll
                for (int nt2 = 0; nt2 < 4; nt2++) {
                    uint32_t kb[4];
                    ldsm4(kb, Kb + (nt2 * 16 * KST2 + ks * 16) * 2 + boffK);
                    mma_f16(sacc[nt2 * 2], qa[ks][0], qa[ks][1], qa[ks][2],
                            qa[ks][3], kb[0], kb[1]);
                    mma_f16(sacc[nt2 * 2 + 1], qa[ks][0], qa[ks][1], qa[ks][2],
                            qa[ks][3], kb[2], kb[3]);
                }
            }

            // ---- mask + scale into exp2 domain ----
            const int rowg0 = q0 + w16 + g;
            const int rowg1 = rowg0 + 8;
#pragma unroll
            for (int nt = 0; nt < 8; nt++) {
                int cl = nt * 8 + 2 * tg;
                int c0 = k0 + cl;
                float kb0 = kmb[buf * FKT + cl];
                float kb1 = kmb[buf * FKT + cl + 1];
                sacc[nt][0] = (c0     <= rowg0) ? sacc[nt][0] * SCL + kb0 : -1e9f;
                sacc[nt][1] = (c0 + 1 <= rowg0) ? sacc[nt][1] * SCL + kb1 : -1e9f;
                sacc[nt][2] = (c0     <= rowg1) ? sacc[nt][2] * SCL + kb0 : -1e9f;
                sacc[nt][3] = (c0 + 1 <= rowg1) ? sacc[nt][3] * SCL + kb1 : -1e9f;
            }

            // ---- online softmax (exp2 domain), P -> fp16 smem ----
            __half2* Ph = (__half2*)(smc + OFF_QP);
#pragma unroll
            for (int r = 0; r < 2; r++) {
                float pm = -1e30f;
#pragma unroll
                for (int nt = 0; nt < 8; nt++)
                    pm = fmaxf(pm, fmaxf(sacc[nt][2 * r], sacc[nt][2 * r + 1]));
                pm = fmaxf(pm, __shfl_xor_sync(0xffffffffu, pm, 1));
                pm = fmaxf(pm, __shfl_xor_sync(0xffffffffu, pm, 2));
                float mn = fmaxf(m2[r], pm);
                float al = exp2p(m2[r] - mn);
                m2[r] = mn;
                float rs = 0.f;
                __half2* prow = Ph + (w16 + g + 8 * r) * 36;
#pragma unroll
                for (int nt = 0; nt < 8; nt++) {
                    float p0 = exp2p(sacc[nt][2 * r] - mn);
                    float p1 = exp2p(sacc[nt][2 * r + 1] - mn);
                    rs += p0 + p1;
                    prow[nt * 4 + tg] = __floats2half2_rn(p0, p1);
                }
                rs += __shfl_xor_sync(0xffffffffu, rs, 1);
                rs += __shfl_xor_sync(0xffffffffu, rs, 2);
                l2[r] = l2[r] * al + rs;
                if (al != 1.f) {
#pragma unroll
                    for (int nt = 0; nt < 16; nt++) {
                        oacc[nt][2 * r]     *= al;
                        oacc[nt][2 * r + 1] *= al;
                    }
                }
            }
            __syncwarp();

            // ---- O += P @ V ----
            const uint32_t Vb = sbase + OFF_V + buf * VSTAGE;
#pragma unroll
            for (int ks = 0; ks < 4; ks++) {
                uint32_t pa[4];
                ldsm4(pa, Pbase + (ks * 16) * 2 + aoffP);
#pragma unroll
                for (int nt2 = 0; nt2 < 8; nt2++) {
                    uint32_t vb[4];
                    ldsm4(vb, Vb + (nt2 * 16 * VST2 + ks * 16) * 2 + boffV);
                    mma_f16(oacc[nt2 * 2], pa[0], pa[1], pa[2], pa[3],
                            vb[0], vb[1]);
                    mma_f16(oacc[nt2 * 2 + 1], pa[0], pa[1], pa[2], pa[3],
                            vb[2], vb[3]);
                }
            }
        }
        __syncthreads();
    }

    // ---- epilogue: normalize + fp16 store to A ----
    float i0 = 1.f / l2[0], i1 = 1.f / l2[1];
    __half* Ar0 = Oc + (size_t)(b * SEQ + q0 + w16 + g) * HID + h * HD;
    __half* Ar1 = Ar0 + (size_t)8 * HID;
#pragma unroll
    for (int nt = 0; nt < 16; nt++) {
        int c = nt * 8 + 2 * tg;
        *(__half2*)(Ar0 + c) = __floats2half2_rn(oacc[nt][0] * i0,
                                                 oacc[nt][1] * i0);
        *(__half2*)(Ar1 + c) = __floats2half2_rn(oacc[nt][2] * i1,
                                                 oacc[nt][3] * i1);
    }
}

// ---------------------------------------------------------------------------
// Launch
// ---------------------------------------------------------------------------
extern "C" void kernel_launch(void* const* d_in, const int* in_sizes, int n_in,
                              void* d_out, int out_size)
{
    const float* hs    = (const float*)d_in[0];
    const float* amask = (const float*)d_in[1];
    const int*   pos   = (const int*)d_in[2];
    const float* Wq    = (const float*)d_in[3];
    const float* Wk    = (const float*)d_in[4];
    const float* Wv    = (const float*)d_in[5];
    const float* Wo    = (const float*)d_in[6];
    float* out = (float*)d_out;

    __half *Xp, *Wqkvp, *Wop, *Qp, *Kp, *Vp, *Vtp, *Ap;
    float *sinp, *cosp;
    cudaGetSymbolAddress((void**)&Xp,    g_X);
    cudaGetSymbolAddress((void**)&Wqkvp, g_Wqkv);
    cudaGetSymbolAddress((void**)&Wop,   g_Wo);
    cudaGetSymbolAddress((void**)&Qp,    g_Q);
    cudaGetSymbolAddress((void**)&Kp,    g_K);
    cudaGetSymbolAddress((void**)&Vp,    g_V);
    cudaGetSymbolAddress((void**)&Vtp,   g_Vt);
    cudaGetSymbolAddress((void**)&Ap,    g_A);
    cudaGetSymbolAddress((void**)&sinp,  g_sin);
    cudaGetSymbolAddress((void**)&cosp,  g_cos);

    cudaFuncSetAttribute(gemm16qkv, cudaFuncAttributeMaxDynamicSharedMemorySize,
                         GEMM_SMEM);
    cudaFuncSetAttribute(gemm16f, cudaFuncAttributeMaxDynamicSharedMemorySize,
                         GEMM_SMEM);
    cudaFuncSetAttribute(flash16, cudaFuncAttributeMaxDynamicSharedMemorySize,
                         FL_SMEM);

    // Convert X; transpose+convert weights; build RoPE table
    {
        int n = MROWS * HID / 4;
        f2h_kernel<<<(n + 255) / 256, 256>>>(hs, Xp, n);
        dim3 blk(32, 8);
        transpose_all<<<dim3(HID / 32, HID / 32, 4), blk>>>(Wq, Wk, Wv, Wo,
                                                            Wqkvp, Wop);
        int nt = MAXPOS * 64;
        rope_table_kernel<<<(nt + 255) / 256, 256>>>(sinp, cosp);
    }

    // Fused QKV projection (256 threads, 64x32 warp tiles)
    gemm16qkv<<<dim3(NQKV / BN, MROWS / BM), 256, GEMM_SMEM>>>(Xp, Wqkvp,
                                                               Qp, Kp, Vp);

    // RoPE on Q and K (table-driven)
    {
        int npq = MROWS * (HID / 2);
        rope_h<<<(npq + 255) / 256, 256>>>(Qp, pos, sinp, cosp, HID, npq);
        int npk = MROWS * (KVW / 2);
        rope_h<<<(npk + 255) / 256, 256>>>(Kp, pos, sinp, cosp, KVW, npk);
    }

    // Transpose V for the PV matmul
    {
        dim3 blk(32, 8);
        vtrans_kernel<<<dim3(SEQ / 32, 128 / 32, 16), blk>>>(Vp, Vtp);
    }

    // FP16 tensor-core flash attention
    flash16<<<dim3(NHEADS * BATCH, SEQ / FQ), 256, FL_SMEM>>>(Qp, Kp, Vtp,
                                                              amask, Ap);

    // Output projection, fp32 output
    gemm16f<<<dim3(HID / BN, MROWS / BM), 256, GEMM_SMEM>>>(Ap, Wop, out,
                                                            MROWS, HID, HID);
}